// round 5
// baseline (speedup 1.0000x reference)
#include <cuda_runtime.h>
#include <cstdint>
#include <cstddef>

#define N_TOKENS   16384
#define IN_F       1024
#define OUT_F      1024
#define BH         32
#define BW         32
#define NB         256
#define N_RB       (OUT_F / BH)   // 32
#define TOK_TILE   128
#define THREADS    128
#define ROWP       36             // row padded to 36 floats (144B): LDS conflicts <= 2-way

__device__ int g_cnt[N_RB];
__device__ int g_blk[N_RB][NB];
__device__ int g_col[N_RB][NB];

__global__ void spmm_prep_kernel(const int* __restrict__ brow,
                                 const int* __restrict__ bcol) {
    int rb = threadIdx.x;
    if (rb >= N_RB) return;
    int c = 0;
    for (int b = 0; b < NB; ++b) {
        if (brow[b] == rb) { g_blk[rb][c] = b; g_col[rb][c] = bcol[b]; ++c; }
    }
    g_cnt[rb] = c;
}

__device__ __forceinline__ unsigned tf32_hi(float v) {
    return __float_as_uint(v) & 0xffffe000u;
}

__device__ __forceinline__ void mma_tf32(float* d, const unsigned* a, const unsigned* b) {
    asm volatile(
        "mma.sync.aligned.m16n8k8.row.col.f32.tf32.tf32.f32 "
        "{%0,%1,%2,%3}, {%4,%5,%6,%7}, {%8,%9}, {%0,%1,%2,%3};"
        : "+f"(d[0]), "+f"(d[1]), "+f"(d[2]), "+f"(d[3])
        : "r"(a[0]), "r"(a[1]), "r"(a[2]), "r"(a[3]), "r"(b[0]), "r"(b[1]));
}

__device__ __forceinline__ void cp16(void* smem_dst, const void* gmem_src) {
    unsigned s = (unsigned)__cvta_generic_to_shared(smem_dst);
    asm volatile("cp.async.cg.shared.global [%0], [%1], 16;" :: "r"(s), "l"(gmem_src));
}

// CTA: 128 tokens x one 32-wide output row-block. 4 warps, each 32 tokens x 32 outs.
// Per sparse block: x-tile(128x32) + W-tile(32x32) staged via cp.async double buffer;
// fragments read from smem with the k-interleave trick (pairs contiguous), split into
// tf32 hi/lo, 3x mma.sync per product for fp32-grade accuracy.
__global__ __launch_bounds__(THREADS, 4)
void spmm_main_kernel(const float* __restrict__ x,
                      const float* __restrict__ w,
                      const float* __restrict__ bias,
                      float* __restrict__ out) {
    __shared__ alignas(16) float sx[2][TOK_TILE][ROWP];  // 36 KB
    __shared__ alignas(16) float sw[2][BH][ROWP];        //  9 KB

    const int rb   = blockIdx.y;
    const int tok0 = blockIdx.x * TOK_TILE;
    const int tid  = threadIdx.x;
    const int wid  = tid >> 5;
    const int lane = tid & 31;
    const int g    = lane >> 2;   // 0..7
    const int c    = lane & 3;    // 0..3

    float acc[2][4][4];
#pragma unroll
    for (int mt = 0; mt < 2; ++mt)
#pragma unroll
        for (int nt = 0; nt < 4; ++nt)
#pragma unroll
            for (int r = 0; r < 4; ++r) acc[mt][nt][r] = 0.0f;

    const int cnt = g_cnt[rb];

    // ---- stage loader: x rows (tid -> row), 8x 16B chunks; W rows op>>3 ----
    auto load_stage = [&](int st, int i) {
        const int b  = g_blk[rb][i];
        const int cb = g_col[rb][i];
        const float* xg = x + (size_t)(tok0 + tid) * IN_F + cb * BW;
#pragma unroll
        for (int j = 0; j < 8; ++j)
            cp16(&sx[st][tid][j * 4], xg + j * 4);
        const float* wb = w + (size_t)b * (BH * BW);
#pragma unroll
        for (int k = 0; k < 2; ++k) {
            const int op = tid + THREADS * k;   // 0..255
            const int r  = op >> 3;
            const int j  = op & 7;
            cp16(&sw[st][r][j * 4], wb + r * BW + j * 4);
        }
        asm volatile("cp.async.commit_group;");
    };

    if (cnt > 0) load_stage(0, 0);

    for (int i = 0; i < cnt; ++i) {
        if (i + 1 < cnt) {
            load_stage((i + 1) & 1, i + 1);
            asm volatile("cp.async.wait_group 1;");
        } else {
            asm volatile("cp.async.wait_group 0;");
        }
        __syncthreads();

        const int st = i & 1;
#pragma unroll
        for (int s = 0; s < 4; ++s) {
            const int kc = 2 * c + 8 * s;   // interleaved k pair base

            unsigned ahi[2][4], alo[2][4];
#pragma unroll
            for (int mt = 0; mt < 2; ++mt) {
                const float2 A0 = *(const float2*)&sx[st][wid * 32 + mt * 16 + g][kc];
                const float2 A1 = *(const float2*)&sx[st][wid * 32 + mt * 16 + g + 8][kc];
                ahi[mt][0] = tf32_hi(A0.x);
                ahi[mt][1] = tf32_hi(A1.x);
                ahi[mt][2] = tf32_hi(A0.y);
                ahi[mt][3] = tf32_hi(A1.y);
                alo[mt][0] = __float_as_uint(A0.x - __uint_as_float(ahi[mt][0]));
                alo[mt][1] = __float_as_uint(A1.x - __uint_as_float(ahi[mt][1]));
                alo[mt][2] = __float_as_uint(A0.y - __uint_as_float(ahi[mt][2]));
                alo[mt][3] = __float_as_uint(A1.y - __uint_as_float(ahi[mt][3]));
            }

#pragma unroll
            for (int nt = 0; nt < 4; ++nt) {
                const float2 B = *(const float2*)&sw[st][nt * 8 + g][kc];
                unsigned bhi[2], blo[2];
                bhi[0] = tf32_hi(B.x);
                bhi[1] = tf32_hi(B.y);
                blo[0] = __float_as_uint(B.x - __uint_as_float(bhi[0]));
                blo[1] = __float_as_uint(B.y - __uint_as_float(bhi[1]));
#pragma unroll
                for (int mt = 0; mt < 2; ++mt) {
                    mma_tf32(acc[mt][nt], ahi[mt], bhi);
                    mma_tf32(acc[mt][nt], ahi[mt], blo);
                    mma_tf32(acc[mt][nt], alo[mt], bhi);
                }
            }
        }
        __syncthreads();   // all warps done reading buf[st] before it is refilled
    }

    // ---- epilogue: add bias, store ----
    const float* bp = bias + rb * BH;
#pragma unroll
    for (int nt = 0; nt < 4; ++nt) {
        const float2 bv = *(const float2*)(bp + nt * 8 + 2 * c);
#pragma unroll
        for (int mt = 0; mt < 2; ++mt) {
            const int row0 = tok0 + wid * 32 + mt * 16 + g;
            float2 o0, o1;
            o0.x = acc[mt][nt][0] + bv.x;
            o0.y = acc[mt][nt][1] + bv.y;
            o1.x = acc[mt][nt][2] + bv.x;
            o1.y = acc[mt][nt][3] + bv.y;
            *(float2*)(out + (size_t)row0       * OUT_F + rb * BH + nt * 8 + 2 * c) = o0;
            *(float2*)(out + (size_t)(row0 + 8) * OUT_F + rb * BH + nt * 8 + 2 * c) = o1;
        }
    }
}

extern "C" void kernel_launch(void* const* d_in, const int* in_sizes, int n_in,
                              void* d_out, int out_size) {
    (void)in_sizes; (void)n_in; (void)out_size;
    const float* x    = (const float*)d_in[0];
    const float* w    = (const float*)d_in[1];
    const float* bias = (const float*)d_in[2];
    const int*   brow = (const int*)d_in[3];
    const int*   bcol = (const int*)d_in[4];
    float* out = (float*)d_out;

    spmm_prep_kernel<<<1, N_RB>>>(brow, bcol);
    dim3 grid(N_TOKENS / TOK_TILE, N_RB);
    spmm_main_kernel<<<grid, THREADS>>>(x, w, bias, out);
}

// round 6
// speedup vs baseline: 1.5214x; 1.5214x over previous
#include <cuda_runtime.h>
#include <cstdint>
#include <cstddef>

#define N_TOKENS   16384
#define IN_F       1024
#define OUT_F      1024
#define BH         32
#define BW         32
#define NB         256
#define N_RB       (OUT_F / BH)   // 32
#define TOK_TILE   256
#define THREADS    256
#define SMAX       11             // W blocks staged in smem (44KB); overflow -> direct LDG

__device__ int g_cnt[N_RB];
__device__ int g_blk[N_RB][NB];
__device__ int g_col[N_RB][NB];

__global__ void spmm_prep_kernel(const int* __restrict__ brow,
                                 const int* __restrict__ bcol) {
    int rb = threadIdx.x;
    if (rb >= N_RB) return;
    int c = 0;
    for (int b = 0; b < NB; ++b) {
        if (brow[b] == rb) { g_blk[rb][c] = b; g_col[rb][c] = bcol[b]; ++c; }
    }
    g_cnt[rb] = c;
}

__device__ __forceinline__ unsigned tf32_hi(float v) {
    return __float_as_uint(v) & 0xffffe000u;
}

__device__ __forceinline__ void mma_tf32(float* d, const unsigned* a, const unsigned* b) {
    asm volatile(
        "mma.sync.aligned.m16n8k8.row.col.f32.tf32.tf32.f32 "
        "{%0,%1,%2,%3}, {%4,%5,%6,%7}, {%8,%9}, {%0,%1,%2,%3};"
        : "+f"(d[0]), "+f"(d[1]), "+f"(d[2]), "+f"(d[3])
        : "r"(a[0]), "r"(a[1]), "r"(a[2]), "r"(a[3]), "r"(b[0]), "r"(b[1]));
}

// CTA: 256 tokens x one 32-wide row-block. 8 independent warps (32 tok x 32 out each).
// k within each k8 MMA step is permuted (lane c owns cols 4c..4c+3 of the 16-col half;
// sub-step uses {4c+2*sub, 4c+2*sub+1}); A and B use the same permutation.
// B is staged ONCE per CTA into smem in fragment order (conflict-free LDS.64);
// A is loaded directly with wide LDG.128 (8 per warp-iter, 64 wavefronts vs 256 in R4).
__global__ __launch_bounds__(THREADS, 2)
void spmm_main_kernel(const float* __restrict__ x,
                      const float* __restrict__ w,
                      const float* __restrict__ bias,
                      float* __restrict__ out) {
    // smB[i][s][nt][lane] : float2 = W[b_i][nt*8+g][16*(s>>1) + 4c + 2*(s&1) .. +1]
    __shared__ alignas(16) float2 smB[SMAX * 16 * 32];   // 44 KB

    const int rb   = blockIdx.y;
    const int tok0 = blockIdx.x * TOK_TILE;
    const int tid  = threadIdx.x;
    const int wid  = tid >> 5;
    const int lane = tid & 31;
    const int g    = lane >> 2;   // 0..7
    const int c    = lane & 3;    // 0..3

    const int cnt = g_cnt[rb];
    const int nstage = cnt < SMAX ? cnt : SMAX;

    // ---- prologue: stage W blocks into smem, fragment-permuted ----
    for (int i = 0; i < nstage; ++i) {
        const float* wb = w + (size_t)g_blk[rb][i] * (BH * BW);
#pragma unroll
        for (int rpt = 0; rpt < 2; ++rpt) {
            const int t = tid + rpt * THREADS;        // 0..511 float2 units
            const float2 v = *(const float2*)(wb + t * 2);
            const int r  = t >> 4;                    // W row 0..31
            const int j  = t & 15;                    // col pair index (col = 2j)
            const int hf = j >> 3;
            const int cc = (j >> 1) & 3;
            const int sb = j & 1;
            const int s  = hf * 2 + sb;
            const int nt = r >> 3;
            const int gg = r & 7;
            smB[(i * 16 + s * 4 + nt) * 32 + gg * 4 + cc] = v;
        }
    }
    __syncthreads();

    float acc[2][4][4];
#pragma unroll
    for (int mt = 0; mt < 2; ++mt)
#pragma unroll
        for (int nt = 0; nt < 4; ++nt)
#pragma unroll
            for (int r = 0; r < 4; ++r) acc[mt][nt][r] = 0.0f;

    const float* xw = x + (size_t)(tok0 + wid * 32) * IN_F;

    for (int i = 0; i < cnt; ++i) {
        const int cb = g_col[rb][i];
        const float* xb = xw + cb * BW;

        // ---- A: 8 wide LDG.128, rows mt*16 + 8a + g, cols 16*hf + 4c ----
        float4 q[2][2][2];
#pragma unroll
        for (int mt = 0; mt < 2; ++mt)
#pragma unroll
            for (int a = 0; a < 2; ++a)
#pragma unroll
                for (int hf = 0; hf < 2; ++hf)
                    q[mt][a][hf] = *(const float4*)
                        (xb + (size_t)(mt * 16 + 8 * a + g) * IN_F + 16 * hf + 4 * c);

        // ---- B overflow path: direct wide LDG ----
        float4 Bq[4][2];
        const bool insm = (i < SMAX);
        if (!insm) {
            const float* wb = w + (size_t)g_blk[rb][i] * (BH * BW);
#pragma unroll
            for (int nt = 0; nt < 4; ++nt)
#pragma unroll
                for (int hf = 0; hf < 2; ++hf)
                    Bq[nt][hf] = *(const float4*)(wb + (nt * 8 + g) * BW + 16 * hf + 4 * c);
        }

#pragma unroll
        for (int hf = 0; hf < 2; ++hf) {
#pragma unroll
            for (int sub = 0; sub < 2; ++sub) {
                const int s = hf * 2 + sub;

                // A fragments for this (hf, sub), both m-tiles
                unsigned ahi[2][4], alo[2][4];
#pragma unroll
                for (int mt = 0; mt < 2; ++mt) {
                    const float a0 = ((const float*)&q[mt][0][hf])[2 * sub];
                    const float a1 = ((const float*)&q[mt][1][hf])[2 * sub];
                    const float a2 = ((const float*)&q[mt][0][hf])[2 * sub + 1];
                    const float a3 = ((const float*)&q[mt][1][hf])[2 * sub + 1];
                    ahi[mt][0] = tf32_hi(a0);
                    ahi[mt][1] = tf32_hi(a1);
                    ahi[mt][2] = tf32_hi(a2);
                    ahi[mt][3] = tf32_hi(a3);
                    alo[mt][0] = __float_as_uint(a0 - __uint_as_float(ahi[mt][0]));
                    alo[mt][1] = __float_as_uint(a1 - __uint_as_float(ahi[mt][1]));
                    alo[mt][2] = __float_as_uint(a2 - __uint_as_float(ahi[mt][2]));
                    alo[mt][3] = __float_as_uint(a3 - __uint_as_float(ahi[mt][3]));
                }

#pragma unroll
                for (int nt = 0; nt < 4; ++nt) {
                    float2 bv;
                    if (insm) {
                        bv = smB[(i * 16 + s * 4 + nt) * 32 + lane];
                    } else {
                        bv.x = ((const float*)&Bq[nt][hf])[2 * sub];
                        bv.y = ((const float*)&Bq[nt][hf])[2 * sub + 1];
                    }
                    unsigned bhi[2], blo[2];
                    bhi[0] = tf32_hi(bv.x);
                    bhi[1] = tf32_hi(bv.y);
                    blo[0] = __float_as_uint(bv.x - __uint_as_float(bhi[0]));
                    blo[1] = __float_as_uint(bv.y - __uint_as_float(bhi[1]));
#pragma unroll
                    for (int mt = 0; mt < 2; ++mt) {
                        mma_tf32(acc[mt][nt], ahi[mt], bhi);
                        mma_tf32(acc[mt][nt], ahi[mt], blo);
                        mma_tf32(acc[mt][nt], alo[mt], bhi);
                    }
                }
            }
        }
    }

    // ---- epilogue: add bias, store ----
    const float* bp = bias + rb * BH;
#pragma unroll
    for (int nt = 0; nt < 4; ++nt) {
        const float2 bv = *(const float2*)(bp + nt * 8 + 2 * c);
#pragma unroll
        for (int mt = 0; mt < 2; ++mt) {
            const int row0 = tok0 + wid * 32 + mt * 16 + g;
            float2 o0, o1;
            o0.x = acc[mt][nt][0] + bv.x;
            o0.y = acc[mt][nt][1] + bv.y;
            o1.x = acc[mt][nt][2] + bv.x;
            o1.y = acc[mt][nt][3] + bv.y;
            *(float2*)(out + (size_t)row0       * OUT_F + rb * BH + nt * 8 + 2 * c) = o0;
            *(float2*)(out + (size_t)(row0 + 8) * OUT_F + rb * BH + nt * 8 + 2 * c) = o1;
        }
    }
}

extern "C" void kernel_launch(void* const* d_in, const int* in_sizes, int n_in,
                              void* d_out, int out_size) {
    (void)in_sizes; (void)n_in; (void)out_size;
    const float* x    = (const float*)d_in[0];
    const float* w    = (const float*)d_in[1];
    const float* bias = (const float*)d_in[2];
    const int*   brow = (const int*)d_in[3];
    const int*   bcol = (const int*)d_in[4];
    float* out = (float*)d_out;

    spmm_prep_kernel<<<1, N_RB>>>(brow, bcol);
    dim3 grid(N_TOKENS / TOK_TILE, N_RB);
    spmm_main_kernel<<<grid, THREADS>>>(x, w, bias, out);
}

// round 7
// speedup vs baseline: 2.1620x; 1.4211x over previous
#include <cuda_runtime.h>
#include <cstdint>
#include <cstddef>

#define N_TOKENS   16384
#define IN_F       1024
#define OUT_F      1024
#define BH         32
#define BW         32
#define NB         256
#define N_RB       (OUT_F / BH)   // 32
#define TOK_TILE   256
#define THREADS    256
#define SMAX       11             // W blocks staged in smem (44KB); overflow -> direct LDG

__device__ int g_cnt[N_RB];
__device__ int g_blk[N_RB][NB];
__device__ int g_col[N_RB][NB];

__global__ void spmm_prep_kernel(const int* __restrict__ brow,
                                 const int* __restrict__ bcol) {
    int rb = threadIdx.x;
    if (rb >= N_RB) return;
    int c = 0;
    for (int b = 0; b < NB; ++b) {
        if (brow[b] == rb) { g_blk[rb][c] = b; g_col[rb][c] = bcol[b]; ++c; }
    }
    g_cnt[rb] = c;
}

// pack two floats into bf16x2: element with LOWER k index in the LOW half.
__device__ __forceinline__ unsigned pack_bf16(float hi, float lo) {
    unsigned d;
    asm("cvt.rn.bf16x2.f32 %0, %1, %2;" : "=r"(d) : "f"(hi), "f"(lo));
    return d;
}
__device__ __forceinline__ float bf_lo(unsigned r) { return __uint_as_float(r << 16); }
__device__ __forceinline__ float bf_hi(unsigned r) { return __uint_as_float(r & 0xffff0000u); }

__device__ __forceinline__ void mma_bf16(float* d, const unsigned* a, const unsigned* b) {
    asm volatile(
        "mma.sync.aligned.m16n8k16.row.col.f32.bf16.bf16.f32 "
        "{%0,%1,%2,%3}, {%4,%5,%6,%7}, {%8,%9}, {%0,%1,%2,%3};"
        : "+f"(d[0]), "+f"(d[1]), "+f"(d[2]), "+f"(d[3])
        : "r"(a[0]), "r"(a[1]), "r"(a[2]), "r"(a[3]), "r"(b[0]), "r"(b[1]));
}

// Build main+residual bf16x2 fragments from a float4 covering phys cols 4c..4c+3.
// reg0 <- (f0,f1) [frag-k 2c,2c+1], reg1 <- (f2,f3) [frag-k 2c+8,2c+9].
__device__ __forceinline__ void split_bf16_pair(const float4& f,
                                                unsigned& m0, unsigned& m1,
                                                unsigned& r0, unsigned& r1) {
    m0 = pack_bf16(f.y, f.x);
    m1 = pack_bf16(f.w, f.z);
    r0 = pack_bf16(f.y - bf_hi(m0), f.x - bf_lo(m0));
    r1 = pack_bf16(f.w - bf_hi(m1), f.z - bf_lo(m1));
}

// CTA: 256 tokens x one 32-wide row-block. 8 independent warps (32 tok x 32 out).
// bf16x3 emulation: a = a_m + a_r, b = b_m + b_r; acc += a_m*b_m + a_m*b_r + a_r*b_m.
// W is staged once per CTA into smem as pre-converted bf16 fragment uint4s
// (b_m0, b_m1, b_r0, b_r1); A loaded via LDG.128 and split in registers.
__global__ __launch_bounds__(THREADS, 2)
void spmm_main_kernel(const float* __restrict__ x,
                      const float* __restrict__ w,
                      const float* __restrict__ bias,
                      float* __restrict__ out) {
    // smB[i][s][nt][lane] = uint4{bm0, bm1, br0, br1}
    __shared__ alignas(16) uint4 smB[SMAX * 2 * 4 * 32];   // 44 KB

    const int rb   = blockIdx.y;
    const int tok0 = blockIdx.x * TOK_TILE;
    const int tid  = threadIdx.x;
    const int wid  = tid >> 5;
    const int lane = tid & 31;
    const int g    = lane >> 2;   // 0..7
    const int c    = lane & 3;    // 0..3

    const int cnt = g_cnt[rb];
    const int nstage = cnt < SMAX ? cnt : SMAX;

    // ---- prologue: stage W blocks as bf16 fragments ----
    for (int i = 0; i < nstage; ++i) {
        const float* wb = w + (size_t)g_blk[rb][i] * (BH * BW);
        // 256 float4s per block, one per thread
        const int r = tid >> 3;          // W out-row 0..31
        const int j = tid & 7;           // float4 index: cols 4j..4j+3
        const int s = j >> 2;            // k16 step
        const int cc = j & 3;
        const float4 f = *(const float4*)(wb + r * BW + j * 4);
        unsigned m0, m1, r0, r1;
        split_bf16_pair(f, m0, m1, r0, r1);
        const int nt = r >> 3;
        const int gg = r & 7;
        smB[((i * 2 + s) * 4 + nt) * 32 + gg * 4 + cc] = make_uint4(m0, m1, r0, r1);
    }
    __syncthreads();

    float acc[2][4][4];
#pragma unroll
    for (int mt = 0; mt < 2; ++mt)
#pragma unroll
        for (int nt = 0; nt < 4; ++nt)
#pragma unroll
            for (int r = 0; r < 4; ++r) acc[mt][nt][r] = 0.0f;

    const float* xw = x + (size_t)(tok0 + wid * 32) * IN_F;

    for (int i = 0; i < cnt; ++i) {
        const int cb = g_col[rb][i];
        const float* xb = xw + cb * BW;

        // ---- A: 8 wide LDG.128; rows mt*16 + 8a + g, cols 16*s + 4c ----
        float4 q[2][2][2];   // [mt][rowhalf a][step s]
#pragma unroll
        for (int mt = 0; mt < 2; ++mt)
#pragma unroll
            for (int a = 0; a < 2; ++a)
#pragma unroll
                for (int s = 0; s < 2; ++s)
                    q[mt][a][s] = *(const float4*)
                        (xb + (size_t)(mt * 16 + 8 * a + g) * IN_F + 16 * s + 4 * c);

        // ---- B overflow path: direct LDG + inline convert ----
        const bool insm = (i < SMAX);
        uint4 Bo[2][4];
        if (!insm) {
            const float* wb = w + (size_t)g_blk[rb][i] * (BH * BW);
#pragma unroll
            for (int s = 0; s < 2; ++s)
#pragma unroll
                for (int nt = 0; nt < 4; ++nt) {
                    const float4 f = *(const float4*)(wb + (nt * 8 + g) * BW + 16 * s + 4 * c);
                    unsigned m0, m1, r0, r1;
                    split_bf16_pair(f, m0, m1, r0, r1);
                    Bo[s][nt] = make_uint4(m0, m1, r0, r1);
                }
        }

#pragma unroll
        for (int s = 0; s < 2; ++s) {
            // A fragments (main + residual) for both m-tiles
            unsigned am[2][4], ar[2][4];
#pragma unroll
            for (int mt = 0; mt < 2; ++mt) {
                split_bf16_pair(q[mt][0][s], am[mt][0], am[mt][2], ar[mt][0], ar[mt][2]);
                split_bf16_pair(q[mt][1][s], am[mt][1], am[mt][3], ar[mt][1], ar[mt][3]);
            }
#pragma unroll
            for (int nt = 0; nt < 4; ++nt) {
                const uint4 bv = insm ? smB[((i * 2 + s) * 4 + nt) * 32 + lane]
                                      : Bo[s][nt];
                const unsigned bm[2] = { bv.x, bv.y };
                const unsigned br[2] = { bv.z, bv.w };
#pragma unroll
                for (int mt = 0; mt < 2; ++mt) {
                    mma_bf16(acc[mt][nt], am[mt], bm);
                    mma_bf16(acc[mt][nt], am[mt], br);
                    mma_bf16(acc[mt][nt], ar[mt], bm);
                }
            }
        }
    }

    // ---- epilogue: add bias, store ----
    const float* bp = bias + rb * BH;
#pragma unroll
    for (int nt = 0; nt < 4; ++nt) {
        const float2 bv = *(const float2*)(bp + nt * 8 + 2 * c);
#pragma unroll
        for (int mt = 0; mt < 2; ++mt) {
            const int row0 = tok0 + wid * 32 + mt * 16 + g;
            float2 o0, o1;
            o0.x = acc[mt][nt][0] + bv.x;
            o0.y = acc[mt][nt][1] + bv.y;
            o1.x = acc[mt][nt][2] + bv.x;
            o1.y = acc[mt][nt][3] + bv.y;
            *(float2*)(out + (size_t)row0       * OUT_F + rb * BH + nt * 8 + 2 * c) = o0;
            *(float2*)(out + (size_t)(row0 + 8) * OUT_F + rb * BH + nt * 8 + 2 * c) = o1;
        }
    }
}

extern "C" void kernel_launch(void* const* d_in, const int* in_sizes, int n_in,
                              void* d_out, int out_size) {
    (void)in_sizes; (void)n_in; (void)out_size;
    const float* x    = (const float*)d_in[0];
    const float* w    = (const float*)d_in[1];
    const float* bias = (const float*)d_in[2];
    const int*   brow = (const int*)d_in[3];
    const int*   bcol = (const int*)d_in[4];
    float* out = (float*)d_out;

    spmm_prep_kernel<<<1, N_RB>>>(brow, bcol);
    dim3 grid(N_TOKENS / TOK_TILE, N_RB);
    spmm_main_kernel<<<grid, THREADS>>>(x, w, bias, out);
}